// round 1
// baseline (speedup 1.0000x reference)
#include <cuda_runtime.h>
#include <math.h>

// Problem dims
#define Dm    512
#define Tt    128
#define NSEQ  8
#define ROWS  (NSEQ*Tt)   // 1024
#define NLAYER 4
#define DFFm  2048
#define NHEAD 4
#define DK    128

// ---------------- scratch (device globals; no allocation) ----------------
__device__ float g_x [ROWS*Dm];
__device__ float g_q [ROWS*Dm];
__device__ float g_k [ROWS*Dm];
__device__ float g_v [ROWS*Dm];
__device__ float g_h [ROWS*Dm];
__device__ float g_ff[ROWS*DFFm];
__device__ float g_s [32*Tt*Tt];      // attn scores/probs (8 seq * 4 heads)
__device__ float g_qs[512*Dm];        // sim q (qe projected)
__device__ float g_ks[512*Dm];        // sim k (ae projected)
__device__ float g_sc[4*Tt*Tt];       // sim scores/probs
__device__ float g_Qc[512*5];
__device__ float g_Kc[512*5];
__device__ float g_G [25];
__device__ float g_pbar[4*Tt];
__device__ float g_Rbar[4*5];

// ---------------- helpers ----------------
__device__ __forceinline__ float blockReduceSum(float v) {
    __shared__ float sh[32];
    __syncthreads();
    int lane = threadIdx.x & 31, w = threadIdx.x >> 5;
    #pragma unroll
    for (int o = 16; o; o >>= 1) v += __shfl_xor_sync(0xffffffffu, v, o);
    if (lane == 0) sh[w] = v;
    __syncthreads();
    int nw = (blockDim.x + 31) >> 5;
    if (w == 0) {
        v = (lane < nw) ? sh[lane] : 0.f;
        #pragma unroll
        for (int o = 16; o; o >>= 1) v += __shfl_xor_sync(0xffffffffu, v, o);
        if (lane == 0) sh[0] = v;
    }
    __syncthreads();
    return sh[0];
}

// batch-offset: mode 0 -> z*stride; mode 1 -> attention head layout (seq,head)
__device__ __forceinline__ long long boff(int mode, long long stride, int z) {
    return mode ? ((long long)(z >> 2) * (Tt * Dm) + (long long)(z & 3) * DK)
                : stride * (long long)z;
}

// ---------------- generic tiled SGEMM (NN): C = A*B (+bias)(+gelu)(+res) ----------------
#define BM 64
#define BN 64
#define BKK 16

__global__ __launch_bounds__(256)
void sgemm_nn(const float* __restrict__ A, int lda,
              const float* __restrict__ B, int ldb,
              const float* __restrict__ bias,
              const float* __restrict__ res, int ldr,
              float* __restrict__ C, int ldc,
              int M, int N, int K, int flags,
              int amode, long long sA, int bmode, long long sB, int cmode, long long sC)
{
    int z = blockIdx.z;
    A += boff(amode, sA, z);
    B += boff(bmode, sB, z);
    C += boff(cmode, sC, z);
    if (res) res += boff(cmode, sC, z);

    __shared__ float As[BKK][BM + 4];
    __shared__ float Bs[BKK][BN + 4];
    const int tid = threadIdx.x;
    const int tr = tid >> 4;
    const int tc = tid & 15;
    const int rowBase = blockIdx.y * BM;
    const int colBase = blockIdx.x * BN;
    float acc[4][4] = {};

    for (int k0 = 0; k0 < K; k0 += BKK) {
        #pragma unroll
        for (int i = 0; i < 4; i++) {
            int idx = tid * 4 + i;
            int r = idx >> 4, c = idx & 15;
            As[c][r] = A[(long long)(rowBase + r) * lda + k0 + c];
        }
        #pragma unroll
        for (int i = 0; i < 4; i++) {
            int idx = tid * 4 + i;
            int r = idx >> 6, c = idx & 63;
            Bs[r][c] = B[(long long)(k0 + r) * ldb + colBase + c];
        }
        __syncthreads();
        #pragma unroll
        for (int kk = 0; kk < BKK; kk++) {
            float a[4], b[4];
            #pragma unroll
            for (int i = 0; i < 4; i++) a[i] = As[kk][tr * 4 + i];
            #pragma unroll
            for (int j = 0; j < 4; j++) b[j] = Bs[kk][tc * 4 + j];
            #pragma unroll
            for (int i = 0; i < 4; i++)
                #pragma unroll
                for (int j = 0; j < 4; j++) acc[i][j] = fmaf(a[i], b[j], acc[i][j]);
        }
        __syncthreads();
    }
    #pragma unroll
    for (int i = 0; i < 4; i++) {
        int r = rowBase + tr * 4 + i;
        #pragma unroll
        for (int j = 0; j < 4; j++) {
            int c = colBase + tc * 4 + j;
            float vv = acc[i][j];
            if (flags & 1) vv += bias[c];
            if (flags & 4) vv = 0.5f * vv * (1.f + erff(vv * 0.7071067811865475f));
            if (flags & 2) vv += res[(long long)r * ldr + c];
            C[(long long)r * ldc + c] = vv;
        }
    }
}

// ---------------- tiled SGEMM (TN): C = scale * A * B^T ----------------
__global__ __launch_bounds__(256)
void sgemm_tn(const float* __restrict__ A, int lda,
              const float* __restrict__ B, int ldb,
              float* __restrict__ C, int ldc,
              int M, int N, int K, float scale,
              int amode, long long sA, int bmode, long long sB, int cmode, long long sC)
{
    int z = blockIdx.z;
    A += boff(amode, sA, z);
    B += boff(bmode, sB, z);
    C += boff(cmode, sC, z);

    __shared__ float As[BKK][BM + 4];
    __shared__ float Bs[BKK][BN + 4];
    const int tid = threadIdx.x;
    const int tr = tid >> 4;
    const int tc = tid & 15;
    const int rowBase = blockIdx.y * BM;
    const int colBase = blockIdx.x * BN;
    float acc[4][4] = {};

    for (int k0 = 0; k0 < K; k0 += BKK) {
        #pragma unroll
        for (int i = 0; i < 4; i++) {
            int idx = tid * 4 + i;
            int r = idx >> 4, c = idx & 15;
            As[c][r] = A[(long long)(rowBase + r) * lda + k0 + c];
        }
        #pragma unroll
        for (int i = 0; i < 4; i++) {
            int idx = tid * 4 + i;
            int r = idx >> 4, c = idx & 15;
            Bs[c][r] = B[(long long)(colBase + r) * ldb + k0 + c];
        }
        __syncthreads();
        #pragma unroll
        for (int kk = 0; kk < BKK; kk++) {
            float a[4], b[4];
            #pragma unroll
            for (int i = 0; i < 4; i++) a[i] = As[kk][tr * 4 + i];
            #pragma unroll
            for (int j = 0; j < 4; j++) b[j] = Bs[kk][tc * 4 + j];
            #pragma unroll
            for (int i = 0; i < 4; i++)
                #pragma unroll
                for (int j = 0; j < 4; j++) acc[i][j] = fmaf(a[i], b[j], acc[i][j]);
        }
        __syncthreads();
    }
    #pragma unroll
    for (int i = 0; i < 4; i++) {
        int r = rowBase + tr * 4 + i;
        #pragma unroll
        for (int j = 0; j < 4; j++) {
            int c = colBase + tc * 4 + j;
            C[(long long)r * ldc + c] = scale * acc[i][j];
        }
    }
}

// ---------------- x = LN(src + pos) (first op) ----------------
__global__ void addposln_kernel(const float* __restrict__ q_emb,
                                const float* __restrict__ a_emb,
                                const float* __restrict__ pos,
                                const float* __restrict__ w,
                                const float* __restrict__ b)
{
    int row = blockIdx.x;
    int t = row & (Tt - 1);
    const float* src = (row < 512) ? (q_emb + (long long)row * Dm)
                                   : (a_emb + (long long)(row - 512) * Dm);
    int d0 = threadIdx.x, d1 = d0 + 256;
    float x0 = src[d0] + pos[t * Dm + d0];
    float x1 = src[d1] + pos[t * Dm + d1];
    float mean = blockReduceSum(x0 + x1) * (1.f / Dm);
    float e0 = x0 - mean, e1 = x1 - mean;
    float var = blockReduceSum(e0 * e0 + e1 * e1) * (1.f / Dm);
    float inv = 1.f / sqrtf(var + 1e-12f);
    g_x[(long long)row * Dm + d0] = w[d0] * e0 * inv + b[d0];
    g_x[(long long)row * Dm + d1] = w[d1] * e1 * inv + b[d1];
}

// ---------------- Y = LN(X) ----------------
__global__ void ln_kernel(const float* __restrict__ X,
                          const float* __restrict__ w,
                          const float* __restrict__ b,
                          float* __restrict__ Y)
{
    int row = blockIdx.x;
    int d0 = threadIdx.x, d1 = d0 + 256;
    float x0 = X[(long long)row * Dm + d0];
    float x1 = X[(long long)row * Dm + d1];
    float mean = blockReduceSum(x0 + x1) * (1.f / Dm);
    float e0 = x0 - mean, e1 = x1 - mean;
    float var = blockReduceSum(e0 * e0 + e1 * e1) * (1.f / Dm);
    float inv = 1.f / sqrtf(var + 1e-12f);
    Y[(long long)row * Dm + d0] = w[d0] * e0 * inv + b[d0];
    Y[(long long)row * Dm + d1] = w[d1] * e1 * inv + b[d1];
}

// ---------------- softmax over rows of 128 (optional x1000 sharpening) ----------------
__global__ void softmax_kernel(float* __restrict__ S, int sharpen)
{
    float* p = S + (long long)blockIdx.x * 128;
    int t = threadIdx.x, lane = t & 31, w = t >> 5;
    __shared__ float sm[4], ss[4], sm2[4], ss2[4];
    float v = p[t];
    float m = v;
    #pragma unroll
    for (int o = 16; o; o >>= 1) m = fmaxf(m, __shfl_xor_sync(0xffffffffu, m, o));
    if (lane == 0) sm[w] = m;
    __syncthreads();
    m = fmaxf(fmaxf(sm[0], sm[1]), fmaxf(sm[2], sm[3]));
    float e = expf(v - m);
    float s = e;
    #pragma unroll
    for (int o = 16; o; o >>= 1) s += __shfl_xor_sync(0xffffffffu, s, o);
    if (lane == 0) ss[w] = s;
    __syncthreads();
    s = ss[0] + ss[1] + ss[2] + ss[3];
    float prob = e / s;
    if (sharpen) {
        float zz = 1000.f * prob;
        float m2 = zz;
        #pragma unroll
        for (int o = 16; o; o >>= 1) m2 = fmaxf(m2, __shfl_xor_sync(0xffffffffu, m2, o));
        if (lane == 0) sm2[w] = m2;
        __syncthreads();
        m2 = fmaxf(fmaxf(sm2[0], sm2[1]), fmaxf(sm2[2], sm2[3]));
        float e2 = expf(zz - m2);
        float s2 = e2;
        #pragma unroll
        for (int o = 16; o; o >>= 1) s2 += __shfl_xor_sync(0xffffffffu, s2, o);
        if (lane == 0) ss2[w] = s2;
        __syncthreads();
        s2 = ss2[0] + ss2[1] + ss2[2] + ss2[3];
        prob = e2 / s2;   // softmax output already in [0,1] -> clip is no-op
    }
    p[t] = prob;
}

// ---------------- Qc/Kc: out[row,c] = dot(X[row,:], ce[c,:]) ----------------
__global__ void proj_concept(const float* __restrict__ X,
                             const float* __restrict__ ce,
                             float* __restrict__ out)
{
    int row = blockIdx.x;
    const float* xr = X + (long long)row * Dm;
    for (int c = 0; c < 5; c++) {
        float partial = 0.f;
        for (int d = threadIdx.x; d < Dm; d += blockDim.x)
            partial += xr[d] * ce[c * Dm + d];
        float tot = blockReduceSum(partial);
        if (threadIdx.x == 0) out[row * 5 + c] = tot;
    }
}

// ---------------- G = ce @ ce^T (5x5) ----------------
__global__ void gram_kernel(const float* __restrict__ ce)
{
    int i = threadIdx.x;
    if (i < 25) {
        int a = i / 5, b2 = i % 5;
        float s = 0.f;
        for (int d = 0; d < Dm; d++) s += ce[a * Dm + d] * ce[b2 * Dm + d];
        g_G[i] = s;
    }
}

// ---------------- add concept correction terms to sim scores ----------------
__global__ void simcorr_kernel(const float* __restrict__ qa,
                               const float* __restrict__ aq)
{
    int b = blockIdx.x >> 7;
    int t = blockIdx.x & 127;
    int s = threadIdx.x;
    __shared__ float sQc[5], sG[25];
    if (s < 5)  sQc[s] = g_Qc[(b * Tt + t) * 5 + s];
    if (s < 25) sG[s] = g_G[s];
    __syncthreads();
    long long base_qa = ((long long)(b * Tt + t) * Tt + s) * 5;
    long long base_aq = ((long long)(b * Tt + s) * Tt + t) * 5;
    float qa5[5], aq5[5], kc[5];
    #pragma unroll
    for (int c = 0; c < 5; c++) {
        qa5[c] = qa[base_qa + c];
        aq5[c] = aq[base_aq + c];
        kc[c]  = g_Kc[(b * Tt + s) * 5 + c];
    }
    float acc = g_sc[b * Tt * Tt + t * Tt + s];
    #pragma unroll
    for (int c = 0; c < 5; c++) acc += aq5[c] * sQc[c] + qa5[c] * kc[c];
    #pragma unroll
    for (int c = 0; c < 5; c++)
        #pragma unroll
        for (int c2 = 0; c2 < 5; c2++) acc += qa5[c] * aq5[c2] * sG[c * 5 + c2];
    g_sc[b * Tt * Tt + t * Tt + s] = acc;
}

// ---------------- pbar[b,s] = mean_t p[b,t,s] ----------------
__global__ void pbar_kernel()
{
    int b = blockIdx.x, s = threadIdx.x;
    float a = 0.f;
    for (int t = 0; t < Tt; t++) a += g_sc[b * Tt * Tt + t * Tt + s];
    g_pbar[b * Tt + s] = a * (1.f / Tt);
}

// ---------------- Rbar[b,c] = mean_t sum_s p[b,t,s]*aq[b,s,t,c] ----------------
__global__ void rbar_kernel(const float* __restrict__ aq)
{
    int b = blockIdx.x, t = threadIdx.x;
    float r[5] = {0.f, 0.f, 0.f, 0.f, 0.f};
    for (int s = 0; s < Tt; s++) {
        float pv = g_sc[b * Tt * Tt + t * Tt + s];
        long long base = ((long long)(b * Tt + s) * Tt + t) * 5;
        #pragma unroll
        for (int c = 0; c < 5; c++) r[c] += pv * aq[base + c];
    }
    for (int c = 0; c < 5; c++) {
        float tot = blockReduceSum(r[c]);
        if (t == 0) g_Rbar[b * 5 + c] = tot * (1.f / Tt);
    }
}

// ---------------- final: m = pbar@k_sim + Rbar@ce; out = m@cls_w + cls_b ----------------
__global__ void final_kernel(const float* __restrict__ ce,
                             const float* __restrict__ cls_w,
                             const float* __restrict__ cls_b,
                             float* __restrict__ out)
{
    __shared__ float m[Dm];
    int b = blockIdx.x, d = threadIdx.x;
    float acc = 0.f;
    for (int s = 0; s < Tt; s++)
        acc += g_pbar[b * Tt + s] * g_ks[(long long)(b * Tt + s) * Dm + d];
    #pragma unroll
    for (int c = 0; c < 5; c++) acc += g_Rbar[b * 5 + c] * ce[c * Dm + d];
    m[d] = acc;
    __syncthreads();
    if (d < 3) {
        float o = cls_b[d];
        for (int k2 = 0; k2 < Dm; k2++) o += m[k2] * cls_w[k2 * 3 + d];
        out[b * 3 + d] = o;
    }
}

// ---------------- host ----------------
extern "C" void kernel_launch(void* const* d_in, const int* in_sizes, int n_in,
                              void* d_out, int out_size)
{
    const float* q_emb    = (const float*)d_in[0];
    const float* a_emb    = (const float*)d_in[1];
    const float* qa_rel   = (const float*)d_in[2];
    const float* aq_rel   = (const float*)d_in[3];
    const float* ce       = (const float*)d_in[4];
    const float* pos_emb  = (const float*)d_in[5];
    const float* pe_w     = (const float*)d_in[6];
    const float* pe_b     = (const float*)d_in[7];
    const float* Wq       = (const float*)d_in[8];
    const float* bq       = (const float*)d_in[9];
    const float* Wk       = (const float*)d_in[10];
    const float* bk       = (const float*)d_in[11];
    const float* Wv       = (const float*)d_in[12];
    const float* bv       = (const float*)d_in[13];
    const float* Wo       = (const float*)d_in[14];
    const float* bo       = (const float*)d_in[15];
    const float* ff1w     = (const float*)d_in[16];
    const float* ff1b     = (const float*)d_in[17];
    const float* ff2w     = (const float*)d_in[18];
    const float* ff2b     = (const float*)d_in[19];
    const float* lnin_w   = (const float*)d_in[20];
    const float* lnin_b   = (const float*)d_in[21];
    const float* lnout_w  = (const float*)d_in[22];
    const float* lnout_b  = (const float*)d_in[23];
    const float* sim_Wq   = (const float*)d_in[24];
    const float* sim_bq   = (const float*)d_in[25];
    const float* sim_Wk   = (const float*)d_in[26];
    const float* sim_bk   = (const float*)d_in[27];
    const float* cls_w    = (const float*)d_in[28];
    const float* cls_b    = (const float*)d_in[29];

    float *x, *q, *k, *v, *h, *ff, *s, *qs, *ks, *sc, *Qc, *Kc;
    cudaGetSymbolAddress((void**)&x,  g_x);
    cudaGetSymbolAddress((void**)&q,  g_q);
    cudaGetSymbolAddress((void**)&k,  g_k);
    cudaGetSymbolAddress((void**)&v,  g_v);
    cudaGetSymbolAddress((void**)&h,  g_h);
    cudaGetSymbolAddress((void**)&ff, g_ff);
    cudaGetSymbolAddress((void**)&s,  g_s);
    cudaGetSymbolAddress((void**)&qs, g_qs);
    cudaGetSymbolAddress((void**)&ks, g_ks);
    cudaGetSymbolAddress((void**)&sc, g_sc);
    cudaGetSymbolAddress((void**)&Qc, g_Qc);
    cudaGetSymbolAddress((void**)&Kc, g_Kc);

    dim3 blk(256);
    const float attn_scale = 0.08838834764831845f;  // 1/sqrt(128)

    // x = LN(emb + pos)
    addposln_kernel<<<ROWS, 256>>>(q_emb, a_emb, pos_emb, pe_w, pe_b);

    for (int i = 0; i < NLAYER; i++) {
        const float* wq = Wq + (long long)i * Dm * Dm;
        const float* wk = Wk + (long long)i * Dm * Dm;
        const float* wv = Wv + (long long)i * Dm * Dm;
        const float* wo = Wo + (long long)i * Dm * Dm;
        const float* f1w = ff1w + (long long)i * Dm * DFFm;
        const float* f2w = ff2w + (long long)i * DFFm * Dm;

        dim3 gEnc(Dm / BN, ROWS / BM, 1);           // (8,16)
        sgemm_nn<<<gEnc, blk>>>(x, Dm, wq, Dm, bq + i * Dm, nullptr, 0, q, Dm,
                                ROWS, Dm, Dm, 1, 0, 0, 0, 0, 0, 0);
        sgemm_nn<<<gEnc, blk>>>(x, Dm, wk, Dm, bk + i * Dm, nullptr, 0, k, Dm,
                                ROWS, Dm, Dm, 1, 0, 0, 0, 0, 0, 0);
        sgemm_nn<<<gEnc, blk>>>(x, Dm, wv, Dm, bv + i * Dm, nullptr, 0, v, Dm,
                                ROWS, Dm, Dm, 1, 0, 0, 0, 0, 0, 0);

        // S = scale * Q K^T per (seq, head)
        dim3 gS(2, 2, 32);
        sgemm_tn<<<gS, blk>>>(q, Dm, k, Dm, s, Tt,
                              Tt, Tt, DK, attn_scale,
                              1, 0, 1, 0, 0, (long long)Tt * Tt);
        softmax_kernel<<<32 * Tt, 128>>>(s, 0);
        // O = P V (written head-interleaved into g_h)
        sgemm_nn<<<gS, blk>>>(s, Tt, v, Dm, nullptr, nullptr, 0, h, Dm,
                              Tt, DK, Tt, 0,
                              0, (long long)Tt * Tt, 1, 0, 1, 0);
        // x = x + O @ Wo + bo
        sgemm_nn<<<gEnc, blk>>>(h, Dm, wo, Dm, bo + i * Dm, x, Dm, x, Dm,
                                ROWS, Dm, Dm, 3, 0, 0, 0, 0, 0, 0);
        // h = LN_in(x)
        ln_kernel<<<ROWS, 256>>>(x, lnin_w + i * Dm, lnin_b + i * Dm, h);
        // ff = gelu(h @ ff1 + b1)
        dim3 gF1(DFFm / BN, ROWS / BM, 1);          // (32,16)
        sgemm_nn<<<gF1, blk>>>(h, Dm, f1w, DFFm, ff1b + i * DFFm, nullptr, 0, ff, DFFm,
                               ROWS, DFFm, Dm, 5, 0, 0, 0, 0, 0, 0);
        // q(temp) = x + ff @ ff2 + b2
        sgemm_nn<<<gEnc, blk>>>(ff, DFFm, f2w, Dm, ff2b + i * Dm, x, Dm, q, Dm,
                                ROWS, Dm, DFFm, 3, 0, 0, 0, 0, 0, 0);
        // x = LN_out(q)
        ln_kernel<<<ROWS, 256>>>(q, lnout_w + i * Dm, lnout_b + i * Dm, x);
    }

    // ---- SimAttn tail ----
    dim3 gP(Dm / BN, 512 / BM, 1);                  // (8,8)
    sgemm_nn<<<gP, blk>>>(x, Dm, sim_Wq, Dm, sim_bq, nullptr, 0, qs, Dm,
                          512, Dm, Dm, 1, 0, 0, 0, 0, 0, 0);
    sgemm_nn<<<gP, blk>>>(x + 512 * Dm, Dm, sim_Wk, Dm, sim_bk, nullptr, 0, ks, Dm,
                          512, Dm, Dm, 1, 0, 0, 0, 0, 0, 0);

    proj_concept<<<512, 256>>>(qs, ce, Qc);
    proj_concept<<<512, 256>>>(ks, ce, Kc);
    gram_kernel<<<1, 32>>>(ce);

    // base scores = q_sim @ k_sim^T per batch
    dim3 gSS(2, 2, 4);
    sgemm_tn<<<gSS, blk>>>(qs, Dm, ks, Dm, sc, Tt,
                           Tt, Tt, Dm, 1.0f,
                           0, (long long)Tt * Dm, 0, (long long)Tt * Dm,
                           0, (long long)Tt * Tt);
    simcorr_kernel<<<512, 128>>>(qa_rel, aq_rel);
    softmax_kernel<<<512, 128>>>(sc, 1);

    pbar_kernel<<<4, 128>>>();
    rbar_kernel<<<4, 128>>>(aq_rel);
    final_kernel<<<4, 512>>>(ce, cls_w, cls_b, (float*)d_out);
}

// round 3
// speedup vs baseline: 1.3798x; 1.3798x over previous
#include <cuda_runtime.h>
#include <math.h>
#include <stdint.h>

// Problem dims
#define Dm    512
#define Tt    128
#define NSEQ  8
#define ROWS  (NSEQ*Tt)   // 1024
#define NLAYER 4
#define DFFm  2048
#define NHEAD 4
#define DK    128

// ---------------- scratch (device globals; no allocation) ----------------
__device__ float g_x [ROWS*Dm];
__device__ float g_q [ROWS*Dm];
__device__ float g_k [ROWS*Dm];
__device__ float g_v [ROWS*Dm];
__device__ float g_h [ROWS*Dm];
__device__ float g_ff[ROWS*DFFm];
__device__ float g_s [32*Tt*Tt];      // attn scores/probs (8 seq * 4 heads)
__device__ float g_qs[512*Dm];        // sim q
__device__ float g_ks[512*Dm];        // sim k
__device__ float g_sc[4*Tt*Tt];       // sim scores/probs
__device__ float g_Qc[512*5];
__device__ float g_Kc[512*5];
__device__ float g_G [25];
__device__ float g_pbar[4*Tt];
__device__ float g_Rbar[4*5];

// ---------------- helpers ----------------
__device__ __forceinline__ float blockReduceSum(float v) {
    __shared__ float sh[32];
    __syncthreads();
    int lane = threadIdx.x & 31, w = threadIdx.x >> 5;
    #pragma unroll
    for (int o = 16; o; o >>= 1) v += __shfl_xor_sync(0xffffffffu, v, o);
    if (lane == 0) sh[w] = v;
    __syncthreads();
    int nw = (blockDim.x + 31) >> 5;
    if (w == 0) {
        v = (lane < nw) ? sh[lane] : 0.f;
        #pragma unroll
        for (int o = 16; o; o >>= 1) v += __shfl_xor_sync(0xffffffffu, v, o);
        if (lane == 0) sh[0] = v;
    }
    __syncthreads();
    return sh[0];
}

// batch-offset: mode 0 -> z*stride; mode 1 -> attention head layout (seq,head)
__device__ __forceinline__ long long boff(int mode, long long stride, int z) {
    return mode ? ((long long)(z >> 2) * (Tt * Dm) + (long long)(z & 3) * DK)
                : stride * (long long)z;
}

__device__ __forceinline__ void cp_async16(void* smem, const void* gmem) {
    uint32_t s = (uint32_t)__cvta_generic_to_shared(smem);
    asm volatile("cp.async.ca.shared.global [%0], [%1], 16;" :: "r"(s), "l"(gmem));
}
#define CP_COMMIT()  asm volatile("cp.async.commit_group;")
#define CP_WAIT1()   asm volatile("cp.async.wait_group 1;")

// 3xTF32 split: f = hi + lo, both tf32-representable
__device__ __forceinline__ void split_tf32(float f, uint32_t& hi, uint32_t& lo) {
    uint32_t h = __float_as_uint(f);
    asm("cvt.rna.tf32.f32 %0, %0;" : "+r"(h));
    float l = f - __uint_as_float(h);
    uint32_t lu = __float_as_uint(l);
    asm("cvt.rna.tf32.f32 %0, %0;" : "+r"(lu));
    hi = h; lo = lu;
}

__device__ __forceinline__ void mma_tf32(float* c, const uint32_t* a, const uint32_t* b) {
    asm volatile(
        "mma.sync.aligned.m16n8k8.row.col.f32.tf32.tf32.f32 "
        "{%0,%1,%2,%3}, {%4,%5,%6,%7}, {%8,%9}, {%0,%1,%2,%3};"
        : "+f"(c[0]), "+f"(c[1]), "+f"(c[2]), "+f"(c[3])
        : "r"(a[0]), "r"(a[1]), "r"(a[2]), "r"(a[3]), "r"(b[0]), "r"(b[1]));
}

// ============ 3xTF32 tensor-core GEMM: C = scale*A*B(^T) (+bias)(+gelu)(+res) ============
// BM=64, BN=128, BK=16, 256 threads, 8 warps (2m x 4n), warp tile 32x32.
// flags: 1=bias, 2=residual add, 4=gelu(before res), 8=select B/bias/C triple by z.
template<int TRANSB>
__global__ __launch_bounds__(256)
void gemm_tc(const float* __restrict__ A, int lda,
             const float* __restrict__ Bm0, const float* __restrict__ Bm1,
             const float* __restrict__ Bm2, int ldb,
             const float* __restrict__ bias0, const float* __restrict__ bias1,
             const float* __restrict__ bias2,
             const float* __restrict__ res, int ldr,
             float* __restrict__ C0, float* __restrict__ C1, float* __restrict__ C2,
             int ldc, int K, int flags, float scale,
             int amode, long long sA, int bmode, long long sB, int cmode, long long sC)
{
    constexpr int BM = 64, BN = 128, BK = 16;
    constexpr int ASTR = 24;                    // 96B rows, 16B aligned
    constexpr int BROW = TRANSB ? BN : BK;
    constexpr int BCOL = TRANSB ? 24 : (BN + 4);

    __shared__ __align__(16) float As[2][BM][ASTR];
    __shared__ __align__(16) float Bs[2][BROW][BCOL];

    const int z = blockIdx.z;
    const float* B = Bm0;
    const float* bias = bias0;
    float* C = C0;
    if (flags & 8) {
        if (z == 1) { B = Bm1; bias = bias1; C = C1; }
        else if (z == 2) { B = Bm2; bias = bias2; C = C2; }
    } else {
        A += boff(amode, sA, z);
        B += boff(bmode, sB, z);
        C += boff(cmode, sC, z);
        if (res) res += boff(cmode, sC, z);
    }

    const int rowBase = blockIdx.y * BM;
    const int colBase = blockIdx.x * BN;
    const int tid = threadIdx.x;
    const int lane = tid & 31;
    const int gid = lane >> 2, tid4 = lane & 3;
    const int w = tid >> 5;
    const int wm = (w >> 2) * 32;
    const int wn = (w & 3) * 32;

    float acc[2][4][4] = {};

    auto loadA = [&](int k0, int buf) {
        int m = tid >> 2, kc = tid & 3;
        cp_async16(&As[buf][m][kc * 4],
                   &A[(long long)(rowBase + m) * lda + k0 + kc * 4]);
    };
    auto loadB = [&](int k0, int buf) {
        if constexpr (TRANSB) {
            #pragma unroll
            for (int i = 0; i < 2; i++) {
                int c = tid + i * 256;
                int n = c >> 2, kc = c & 3;
                cp_async16(&Bs[buf][n][kc * 4],
                           &B[(long long)(colBase + n) * ldb + k0 + kc * 4]);
            }
        } else {
            #pragma unroll
            for (int i = 0; i < 2; i++) {
                int c = tid + i * 256;
                int k = c >> 5, nc = c & 31;
                cp_async16(&Bs[buf][k][nc * 4],
                           &B[(long long)(k0 + k) * ldb + colBase + nc * 4]);
            }
        }
    };

    const int NIT = K / BK;
    loadA(0, 0); loadB(0, 0);
    CP_COMMIT();

    for (int it = 0; it < NIT; it++) {
        const int cur = it & 1;
        if (it + 1 < NIT) { loadA((it + 1) * BK, cur ^ 1); loadB((it + 1) * BK, cur ^ 1); }
        CP_COMMIT();
        CP_WAIT1();
        __syncthreads();

        #pragma unroll
        for (int ks = 0; ks < 2; ks++) {
            const int kk = ks * 8;
            uint32_t ah[2][4], al[2][4], bh[4][2], bl[4][2];
            #pragma unroll
            for (int mt = 0; mt < 2; mt++) {
                int m = wm + mt * 16 + gid;
                split_tf32(As[cur][m][kk + tid4],          ah[mt][0], al[mt][0]);
                split_tf32(As[cur][m + 8][kk + tid4],      ah[mt][1], al[mt][1]);
                split_tf32(As[cur][m][kk + tid4 + 4],      ah[mt][2], al[mt][2]);
                split_tf32(As[cur][m + 8][kk + tid4 + 4],  ah[mt][3], al[mt][3]);
            }
            #pragma unroll
            for (int nt = 0; nt < 4; nt++) {
                int n = wn + nt * 8 + gid;
                float b0, b1;
                if constexpr (TRANSB) {
                    b0 = Bs[cur][n][kk + tid4];
                    b1 = Bs[cur][n][kk + tid4 + 4];
                } else {
                    b0 = Bs[cur][kk + tid4][n];
                    b1 = Bs[cur][kk + tid4 + 4][n];
                }
                split_tf32(b0, bh[nt][0], bl[nt][0]);
                split_tf32(b1, bh[nt][1], bl[nt][1]);
            }
            #pragma unroll
            for (int mt = 0; mt < 2; mt++)
                #pragma unroll
                for (int nt = 0; nt < 4; nt++) {
                    mma_tf32(acc[mt][nt], al[mt], bh[nt]);   // lo*hi
                    mma_tf32(acc[mt][nt], ah[mt], bl[nt]);   // hi*lo
                    mma_tf32(acc[mt][nt], ah[mt], bh[nt]);   // hi*hi last (largest)
                }
        }
        __syncthreads();
    }

    // epilogue
    #pragma unroll
    for (int mt = 0; mt < 2; mt++) {
        #pragma unroll
        for (int nt = 0; nt < 4; nt++) {
            int r0 = rowBase + wm + mt * 16 + gid;
            int col = colBase + wn + nt * 8 + tid4 * 2;
            #pragma unroll
            for (int half = 0; half < 2; half++) {
                int r = r0 + half * 8;
                float v0 = acc[mt][nt][half * 2 + 0] * scale;
                float v1 = acc[mt][nt][half * 2 + 1] * scale;
                if (flags & 1) { v0 += bias[col]; v1 += bias[col + 1]; }
                if (flags & 4) {
                    v0 = 0.5f * v0 * (1.f + erff(v0 * 0.7071067811865475f));
                    v1 = 0.5f * v1 * (1.f + erff(v1 * 0.7071067811865475f));
                }
                if (flags & 2) {
                    float2 rv = *(const float2*)&res[(long long)r * ldr + col];
                    v0 += rv.x; v1 += rv.y;
                }
                float2 out; out.x = v0; out.y = v1;
                *(float2*)&C[(long long)r * ldc + col] = out;
            }
        }
    }
}

// ---------------- fp32 tiled SGEMM (NN) for sim tail ----------------
#define BMf 64
#define BNf 64
#define BKf 16

__global__ __launch_bounds__(256)
void sgemm_nn(const float* __restrict__ A, int lda,
              const float* __restrict__ B, int ldb,
              const float* __restrict__ bias,
              float* __restrict__ C, int ldc,
              int M, int N, int K)
{
    __shared__ float As[BKf][BMf + 4];
    __shared__ float Bs[BKf][BNf + 4];
    const int tid = threadIdx.x;
    const int tr = tid >> 4;
    const int tc = tid & 15;
    const int rowBase = blockIdx.y * BMf;
    const int colBase = blockIdx.x * BNf;
    float acc[4][4] = {};

    for (int k0 = 0; k0 < K; k0 += BKf) {
        #pragma unroll
        for (int i = 0; i < 4; i++) {
            int idx = tid * 4 + i;
            int r = idx >> 4, c = idx & 15;
            As[c][r] = A[(long long)(rowBase + r) * lda + k0 + c];
        }
        #pragma unroll
        for (int i = 0; i < 4; i++) {
            int idx = tid * 4 + i;
            int r = idx >> 6, c = idx & 63;
            Bs[r][c] = B[(long long)(k0 + r) * ldb + colBase + c];
        }
        __syncthreads();
        #pragma unroll
        for (int kk = 0; kk < BKf; kk++) {
            float a[4], b[4];
            #pragma unroll
            for (int i = 0; i < 4; i++) a[i] = As[kk][tr * 4 + i];
            #pragma unroll
            for (int j = 0; j < 4; j++) b[j] = Bs[kk][tc * 4 + j];
            #pragma unroll
            for (int i = 0; i < 4; i++)
                #pragma unroll
                for (int j = 0; j < 4; j++) acc[i][j] = fmaf(a[i], b[j], acc[i][j]);
        }
        __syncthreads();
    }
    #pragma unroll
    for (int i = 0; i < 4; i++) {
        int r = rowBase + tr * 4 + i;
        #pragma unroll
        for (int j = 0; j < 4; j++) {
            int c = colBase + tc * 4 + j;
            C[(long long)r * ldc + c] = acc[i][j] + bias[c];
        }
    }
}

// ---------------- fp32 tiled SGEMM (TN): C = A * B^T per batch z ----------------
__global__ __launch_bounds__(256)
void sgemm_tn(const float* __restrict__ A, int lda,
              const float* __restrict__ B, int ldb,
              float* __restrict__ C, int ldc,
              int K, long long sA, long long sB, long long sC)
{
    int z = blockIdx.z;
    A += sA * z; B += sB * z; C += sC * z;

    __shared__ float As[BKf][BMf + 4];
    __shared__ float Bs[BKf][BNf + 4];
    const int tid = threadIdx.x;
    const int tr = tid >> 4;
    const int tc = tid & 15;
    const int rowBase = blockIdx.y * BMf;
    const int colBase = blockIdx.x * BNf;
    float acc[4][4] = {};

    for (int k0 = 0; k0 < K; k0 += BKf) {
        #pragma unroll
        for (int i = 0; i < 4; i++) {
            int idx = tid * 4 + i;
            int r = idx >> 4, c = idx & 15;
            As[c][r] = A[(long long)(rowBase + r) * lda + k0 + c];
        }
        #pragma unroll
        for (int i = 0; i < 4; i++) {
            int idx = tid * 4 + i;
            int r = idx >> 4, c = idx & 15;
            Bs[c][r] = B[(long long)(colBase + r) * ldb + k0 + c];
        }
        __syncthreads();
        #pragma unroll
        for (int kk = 0; kk < BKf; kk++) {
            float a[4], b[4];
            #pragma unroll
            for (int i = 0; i < 4; i++) a[i] = As[kk][tr * 4 + i];
            #pragma unroll
            for (int j = 0; j < 4; j++) b[j] = Bs[kk][tc * 4 + j];
            #pragma unroll
            for (int i = 0; i < 4; i++)
                #pragma unroll
                for (int j = 0; j < 4; j++) acc[i][j] = fmaf(a[i], b[j], acc[i][j]);
        }
        __syncthreads();
    }
    #pragma unroll
    for (int i = 0; i < 4; i++) {
        int r = rowBase + tr * 4 + i;
        #pragma unroll
        for (int j = 0; j < 4; j++) {
            int c = colBase + tc * 4 + j;
            C[(long long)r * ldc + c] = acc[i][j];
        }
    }
}

// ---------------- x = LN(src + pos) ----------------
__global__ void addposln_kernel(const float* __restrict__ q_emb,
                                const float* __restrict__ a_emb,
                                const float* __restrict__ pos,
                                const float* __restrict__ w,
                                const float* __restrict__ b)
{
    int row = blockIdx.x;
    int t = row & (Tt - 1);
    const float* src = (row < 512) ? (q_emb + (long long)row * Dm)
                                   : (a_emb + (long long)(row - 512) * Dm);
    int d0 = threadIdx.x, d1 = d0 + 256;
    float x0 = src[d0] + pos[t * Dm + d0];
    float x1 = src[d1] + pos[t * Dm + d1];
    float mean = blockReduceSum(x0 + x1) * (1.f / Dm);
    float e0 = x0 - mean, e1 = x1 - mean;
    float var = blockReduceSum(e0 * e0 + e1 * e1) * (1.f / Dm);
    float inv = 1.f / sqrtf(var + 1e-12f);
    g_x[(long long)row * Dm + d0] = w[d0] * e0 * inv + b[d0];
    g_x[(long long)row * Dm + d1] = w[d1] * e1 * inv + b[d1];
}

// ---------------- Y = LN(X) ----------------
__global__ void ln_kernel(const float* __restrict__ X,
                          const float* __restrict__ w,
                          const float* __restrict__ b,
                          float* __restrict__ Y)
{
    int row = blockIdx.x;
    int d0 = threadIdx.x, d1 = d0 + 256;
    float x0 = X[(long long)row * Dm + d0];
    float x1 = X[(long long)row * Dm + d1];
    float mean = blockReduceSum(x0 + x1) * (1.f / Dm);
    float e0 = x0 - mean, e1 = x1 - mean;
    float var = blockReduceSum(e0 * e0 + e1 * e1) * (1.f / Dm);
    float inv = 1.f / sqrtf(var + 1e-12f);
    Y[(long long)row * Dm + d0] = w[d0] * e0 * inv + b[d0];
    Y[(long long)row * Dm + d1] = w[d1] * e1 * inv + b[d1];
}

// ---------------- softmax over rows of 128 (optional x1000 sharpening) ----------------
__global__ void softmax_kernel(float* __restrict__ S, int sharpen)
{
    float* p = S + (long long)blockIdx.x * 128;
    int t = threadIdx.x, lane = t & 31, w = t >> 5;
    __shared__ float sm[4], ss[4], sm2[4], ss2[4];
    float v = p[t];
    float m = v;
    #pragma unroll
    for (int o = 16; o; o >>= 1) m = fmaxf(m, __shfl_xor_sync(0xffffffffu, m, o));
    if (lane == 0) sm[w] = m;
    __syncthreads();
    m = fmaxf(fmaxf(sm[0], sm[1]), fmaxf(sm[2], sm[3]));
    float e = expf(v - m);
    float s = e;
    #pragma unroll
    for (int o = 16; o; o >>= 1) s += __shfl_xor_sync(0xffffffffu, s, o);
    if (lane == 0) ss[w] = s;
    __syncthreads();
    s = ss[0] + ss[1] + ss[2] + ss[3];
    float prob = e / s;
    if (sharpen) {
        float zz = 1000.f * prob;
        float m2 = zz;
        #pragma unroll
        for (int o = 16; o; o >>= 1) m2 = fmaxf(m2, __shfl_xor_sync(0xffffffffu, m2, o));
        if (lane == 0) sm2[w] = m2;
        __syncthreads();
        m2 = fmaxf(fmaxf(sm2[0], sm2[1]), fmaxf(sm2[2], sm2[3]));
        float e2 = expf(zz - m2);
        float s2 = e2;
        #pragma unroll
        for (int o = 16; o; o >>= 1) s2 += __shfl_xor_sync(0xffffffffu, s2, o);
        if (lane == 0) ss2[w] = s2;
        __syncthreads();
        s2 = ss2[0] + ss2[1] + ss2[2] + ss2[3];
        prob = e2 / s2;
    }
    p[t] = prob;
}

// ---------------- Qc/Kc: out[row,c] = dot(X[row,:], ce[c,:]) ----------------
__global__ void proj_concept(const float* __restrict__ X,
                             const float* __restrict__ ce,
                             float* __restrict__ out)
{
    int row = blockIdx.x;
    const float* xr = X + (long long)row * Dm;
    for (int c = 0; c < 5; c++) {
        float partial = 0.f;
        for (int d = threadIdx.x; d < Dm; d += blockDim.x)
            partial += xr[d] * ce[c * Dm + d];
        float tot = blockReduceSum(partial);
        if (threadIdx.x == 0) out[row * 5 + c] = tot;
    }
}

// ---------------- G = ce @ ce^T (5x5) ----------------
__global__ void gram_kernel(const float* __restrict__ ce)
{
    int i = threadIdx.x;
    if (i < 25) {
        int a = i / 5, b2 = i % 5;
        float s = 0.f;
        for (int d = 0; d < Dm; d++) s += ce[a * Dm + d] * ce[b2 * Dm + d];
        g_G[i] = s;
    }
}

// ---------------- add concept correction terms to sim scores ----------------
__global__ void simcorr_kernel(const float* __restrict__ qa,
                               const float* __restrict__ aq)
{
    int b = blockIdx.x >> 7;
    int t = blockIdx.x & 127;
    int s = threadIdx.x;
    __shared__ float sQc[5], sG[25];
    if (s < 5)  sQc[s] = g_Qc[(b * Tt + t) * 5 + s];
    if (s < 25) sG[s] = g_G[s];
    __syncthreads();
    long long base_qa = ((long long)(b * Tt + t) * Tt + s) * 5;
    long long base_aq = ((long long)(b * Tt + s) * Tt + t) * 5;
    float qa5[5], aq5[5], kc[5];
    #pragma unroll
    for (int c = 0; c < 5; c++) {
        qa5[c] = qa[base_qa + c];
        aq5[c] = aq[base_aq + c];
        kc[c]  = g_Kc[(b * Tt + s) * 5 + c];
    }
    float acc = g_sc[b * Tt * Tt + t * Tt + s];
    #pragma unroll
    for (int c = 0; c < 5; c++) acc += aq5[c] * sQc[c] + qa5[c] * kc[c];
    #pragma unroll
    for (int c = 0; c < 5; c++)
        #pragma unroll
        for (int c2 = 0; c2 < 5; c2++) acc += qa5[c] * aq5[c2] * sG[c * 5 + c2];
    g_sc[b * Tt * Tt + t * Tt + s] = acc;
}

// ---------------- pbar[b,s] = mean_t p[b,t,s] ----------------
__global__ void pbar_kernel()
{
    int b = blockIdx.x, s = threadIdx.x;
    float a = 0.f;
    for (int t = 0; t < Tt; t++) a += g_sc[b * Tt * Tt + t * Tt + s];
    g_pbar[b * Tt + s] = a * (1.f / Tt);
}

// ---------------- Rbar[b,c] = mean_t sum_s p[b,t,s]*aq[b,s,t,c] ----------------
__global__ void rbar_kernel(const float* __restrict__ aq)
{
    int b = blockIdx.x, t = threadIdx.x;
    float r[5] = {0.f, 0.f, 0.f, 0.f, 0.f};
    for (int s = 0; s < Tt; s++) {
        float pv = g_sc[b * Tt * Tt + t * Tt + s];
        long long base = ((long long)(b * Tt + s) * Tt + t) * 5;
        #pragma unroll
        for (int c = 0; c < 5; c++) r[c] += pv * aq[base + c];
    }
    for (int c = 0; c < 5; c++) {
        float tot = blockReduceSum(r[c]);
        if (t == 0) g_Rbar[b * 5 + c] = tot * (1.f / Tt);
    }
}

// ---------------- final ----------------
__global__ void final_kernel(const float* __restrict__ ce,
                             const float* __restrict__ cls_w,
                             const float* __restrict__ cls_b,
                             float* __restrict__ out)
{
    __shared__ float m[Dm];
    int b = blockIdx.x, d = threadIdx.x;
    float acc = 0.f;
    for (int s = 0; s < Tt; s++)
        acc += g_pbar[b * Tt + s] * g_ks[(long long)(b * Tt + s) * Dm + d];
    #pragma unroll
    for (int c = 0; c < 5; c++) acc += g_Rbar[b * 5 + c] * ce[c * Dm + d];
    m[d] = acc;
    __syncthreads();
    if (d < 3) {
        float o = cls_b[d];
        for (int k2 = 0; k2 < Dm; k2++) o += m[k2] * cls_w[k2 * 3 + d];
        out[b * 3 + d] = o;
    }
}

// ---------------- host ----------------
extern "C" void kernel_launch(void* const* d_in, const int* in_sizes, int n_in,
                              void* d_out, int out_size)
{
    const float* q_emb    = (const float*)d_in[0];
    const float* a_emb    = (const float*)d_in[1];
    const float* qa_rel   = (const float*)d_in[2];
    const float* aq_rel   = (const float*)d_in[3];
    const float* ce       = (const float*)d_in[4];
    const float* pos_emb  = (const float*)d_in[5];
    const float* pe_w     = (const float*)d_in[6];
    const float* pe_b     = (const float*)d_in[7];
    const float* Wq       = (const float*)d_in[8];
    const float* bq       = (const float*)d_in[9];
    const float* Wk       = (const float*)d_in[10];
    const float* bk       = (const float*)d_in[11];
    const float* Wv       = (const float*)d_in[12];
    const float* bv       = (const float*)d_in[13];
    const float* Wo       = (const float*)d_in[14];
    const float* bo       = (const float*)d_in[15];
    const float* ff1w     = (const float*)d_in[16];
    const float* ff1b     = (const float*)d_in[17];
    const float* ff2w     = (const float*)d_in[18];
    const float* ff2b     = (const float*)d_in[19];
    const float* lnin_w   = (const float*)d_in[20];
    const float* lnin_b   = (const float*)d_in[21];
    const float* lnout_w  = (const float*)d_in[22];
    const float* lnout_b  = (const float*)d_in[23];
    const float* sim_Wq   = (const float*)d_in[24];
    const float* sim_bq   = (const float*)d_in[25];
    const float* sim_Wk   = (const float*)d_in[26];
    const float* sim_bk   = (const float*)d_in[27];
    const float* cls_w    = (const float*)d_in[28];
    const float* cls_b    = (const float*)d_in[29];

    float *x, *q, *k, *v, *h, *ff, *s, *qs, *ks, *sc, *Qc, *Kc;
    cudaGetSymbolAddress((void**)&x,  g_x);
    cudaGetSymbolAddress((void**)&q,  g_q);
    cudaGetSymbolAddress((void**)&k,  g_k);
    cudaGetSymbolAddress((void**)&v,  g_v);
    cudaGetSymbolAddress((void**)&h,  g_h);
    cudaGetSymbolAddress((void**)&ff, g_ff);
    cudaGetSymbolAddress((void**)&s,  g_s);
    cudaGetSymbolAddress((void**)&qs, g_qs);
    cudaGetSymbolAddress((void**)&ks, g_ks);
    cudaGetSymbolAddress((void**)&sc, g_sc);
    cudaGetSymbolAddress((void**)&Qc, g_Qc);
    cudaGetSymbolAddress((void**)&Kc, g_Kc);

    const float attn_scale = 0.08838834764831845f;  // 1/sqrt(128)
    dim3 blk(256);

    addposln_kernel<<<ROWS, 256>>>(q_emb, a_emb, pos_emb, pe_w, pe_b);

    for (int i = 0; i < NLAYER; i++) {
        const float* wq = Wq + (long long)i * Dm * Dm;
        const float* wk = Wk + (long long)i * Dm * Dm;
        const float* wv = Wv + (long long)i * Dm * Dm;
        const float* wo = Wo + (long long)i * Dm * Dm;
        const float* f1w = ff1w + (long long)i * Dm * DFFm;
        const float* f2w = ff2w + (long long)i * DFFm * Dm;

        // fused QKV: z selects (W, bias, out)
        gemm_tc<0><<<dim3(4, 16, 3), blk>>>(
            x, Dm, wq, wk, wv, Dm, bq + i * Dm, bk + i * Dm, bv + i * Dm,
            nullptr, 0, q, k, v, Dm, Dm, 1 | 8, 1.f, 0, 0, 0, 0, 0, 0);

        // S = scale * Q K^T per (seq,head)
        gemm_tc<1><<<dim3(1, 2, 32), blk>>>(
            q, Dm, k, nullptr, nullptr, Dm, nullptr, nullptr, nullptr,
            nullptr, 0, s, nullptr, nullptr, Tt, DK, 0, attn_scale,
            1, 0, 1, 0, 0, (long long)Tt * Tt);
        softmax_kernel<<<32 * Tt, 128>>>(s, 0);
        // O = P V (head-interleaved into g_h)
        gemm_tc<0><<<dim3(1, 2, 32), blk>>>(
            s, Tt, v, nullptr, nullptr, Dm, nullptr, nullptr, nullptr,
            nullptr, 0, h, nullptr, nullptr, Dm, Tt, 0, 1.f,
            0, (long long)Tt * Tt, 1, 0, 1, 0);
        // x = x + O @ Wo + bo
        gemm_tc<0><<<dim3(4, 16, 1), blk>>>(
            h, Dm, wo, nullptr, nullptr, Dm, bo + i * Dm, nullptr, nullptr,
            x, Dm, x, nullptr, nullptr, Dm, Dm, 1 | 2, 1.f, 0, 0, 0, 0, 0, 0);
        // h = LN_in(x)
        ln_kernel<<<ROWS, 256>>>(x, lnin_w + i * Dm, lnin_b + i * Dm, h);
        // ff = gelu(h @ ff1 + b1)
        gemm_tc<0><<<dim3(16, 16, 1), blk>>>(
            h, Dm, f1w, nullptr, nullptr, DFFm, ff1b + i * DFFm, nullptr, nullptr,
            nullptr, 0, ff, nullptr, nullptr, DFFm, Dm, 1 | 4, 1.f, 0, 0, 0, 0, 0, 0);
        // q(tmp) = x + ff @ ff2 + b2
        gemm_tc<0><<<dim3(4, 16, 1), blk>>>(
            ff, DFFm, f2w, nullptr, nullptr, Dm, ff2b + i * Dm, nullptr, nullptr,
            x, Dm, q, nullptr, nullptr, Dm, DFFm, 1 | 2, 1.f, 0, 0, 0, 0, 0, 0);
        // x = LN_out(q)
        ln_kernel<<<ROWS, 256>>>(q, lnout_w + i * Dm, lnout_b + i * Dm, x);
    }

    // ---- SimAttn tail (fp32 for precision under sharpened softmax) ----
    dim3 gP(Dm / BNf, 512 / BMf, 1);
    sgemm_nn<<<gP, blk>>>(x, Dm, sim_Wq, Dm, sim_bq, qs, Dm, 512, Dm, Dm);
    sgemm_nn<<<gP, blk>>>(x + 512 * Dm, Dm, sim_Wk, Dm, sim_bk, ks, Dm, 512, Dm, Dm);

    proj_concept<<<512, 256>>>(qs, ce, Qc);
    proj_concept<<<512, 256>>>(ks, ce, Kc);
    gram_kernel<<<1, 32>>>(ce);

    dim3 gSS(2, 2, 4);
    sgemm_tn<<<gSS, blk>>>(qs, Dm, ks, Dm, sc, Tt, Dm,
                           (long long)Tt * Dm, (long long)Tt * Dm, (long long)Tt * Tt);
    simcorr_kernel<<<512, 128>>>(qa_rel, aq_rel);
    softmax_kernel<<<512, 128>>>(sc, 1);

    pbar_kernel<<<4, 128>>>();
    rbar_kernel<<<4, 128>>>(aq_rel);
    final_kernel<<<4, 512>>>(ce, cls_w, cls_b, (float*)d_out);
}

// round 5
// speedup vs baseline: 2.1546x; 1.5615x over previous
#include <cuda_runtime.h>
#include <math.h>
#include <stdint.h>

// Problem dims
#define Dm    512
#define Tt    128
#define NSEQ  8
#define ROWS  (NSEQ*Tt)   // 1024
#define NLAYER 4
#define DFFm  2048
#define NHEAD 4
#define DK    128

// ---------------- scratch (device globals; no allocation) ----------------
__device__ __align__(256) float g_x [ROWS*Dm];
__device__ __align__(256) float g_q [ROWS*Dm];
__device__ __align__(256) float g_k [ROWS*Dm];
__device__ __align__(256) float g_v [ROWS*Dm];
__device__ __align__(256) float g_h [ROWS*Dm];
__device__ __align__(256) float g_ff[ROWS*DFFm];
__device__ __align__(256) float g_s [32*Tt*Tt];
__device__ __align__(256) float g_qs[512*Dm];
__device__ __align__(256) float g_ks[512*Dm];
__device__ __align__(256) float g_sc[4*Tt*Tt];
__device__ __align__(256) float g_Qc[512*5];
__device__ __align__(256) float g_Kc[512*5];
__device__ __align__(256) float g_G [25];
__device__ __align__(256) float g_pbar[4*Tt];
__device__ __align__(256) float g_Rbar[4*5];

// ---------------- helpers ----------------
__device__ __forceinline__ float blockReduceSum(float v) {
    __shared__ float sh[32];
    __syncthreads();
    int lane = threadIdx.x & 31, w = threadIdx.x >> 5;
    #pragma unroll
    for (int o = 16; o; o >>= 1) v += __shfl_xor_sync(0xffffffffu, v, o);
    if (lane == 0) sh[w] = v;
    __syncthreads();
    int nw = (blockDim.x + 31) >> 5;
    if (w == 0) {
        v = (lane < nw) ? sh[lane] : 0.f;
        #pragma unroll
        for (int o = 16; o; o >>= 1) v += __shfl_xor_sync(0xffffffffu, v, o);
        if (lane == 0) sh[0] = v;
    }
    __syncthreads();
    return sh[0];
}

// batch-offset: mode 0 -> z*stride; mode 1 -> attention head layout (seq,head)
__device__ __forceinline__ long long boff(int mode, long long stride, int z) {
    return mode ? ((long long)(z >> 2) * (Tt * Dm) + (long long)(z & 3) * DK)
                : stride * (long long)z;
}

__device__ __forceinline__ void cp_async16(void* smem, const void* gmem) {
    uint32_t s = (uint32_t)__cvta_generic_to_shared(smem);
    asm volatile("cp.async.ca.shared.global [%0], [%1], 16;" :: "r"(s), "l"(gmem));
}
#define CP_COMMIT()  asm volatile("cp.async.commit_group;")
#define CP_WAIT1()   asm volatile("cp.async.wait_group 1;")

// 3xTF32 split: f = hi + lo, both tf32-representable
__device__ __forceinline__ void split_tf32(float f, uint32_t& hi, uint32_t& lo) {
    uint32_t h = __float_as_uint(f);
    asm("cvt.rna.tf32.f32 %0, %0;" : "+r"(h));
    float l = f - __uint_as_float(h);
    uint32_t lu = __float_as_uint(l);
    asm("cvt.rna.tf32.f32 %0, %0;" : "+r"(lu));
    hi = h; lo = lu;
}

__device__ __forceinline__ void mma_tf32(float* c, const uint32_t* a, const uint32_t* b) {
    asm volatile(
        "mma.sync.aligned.m16n8k8.row.col.f32.tf32.tf32.f32 "
        "{%0,%1,%2,%3}, {%4,%5,%6,%7}, {%8,%9}, {%0,%1,%2,%3};"
        : "+f"(c[0]), "+f"(c[1]), "+f"(c[2]), "+f"(c[3])
        : "r"(a[0]), "r"(a[1]), "r"(a[2]), "r"(a[3]), "r"(b[0]), "r"(b[1]));
}

// ============ 3xTF32 tensor-core GEMM ============
// BM=64, BN=64, BK=32, 128 threads (4 warps, 2x2), warp tile 32x32.
// flags: 1=bias, 2=residual add, 4=gelu(before res), 8=select B/bias/C triple by z.
template<int TRANSB>
__global__ __launch_bounds__(128, 4)
void gemm_tc(const float* __restrict__ A, int lda,
             const float* __restrict__ Bm0, const float* __restrict__ Bm1,
             const float* __restrict__ Bm2, int ldb,
             const float* __restrict__ bias0, const float* __restrict__ bias1,
             const float* __restrict__ bias2,
             const float* __restrict__ res, int ldr,
             float* __restrict__ C0, float* __restrict__ C1, float* __restrict__ C2,
             int ldc, int K, int flags, float scale,
             int amode, long long sA, int bmode, long long sB, int cmode, long long sC)
{
    constexpr int BM = 64, BN = 64, BK = 32;
    constexpr int ASTR = 36;     // 64x36 floats, frag bank = 4*gid+tid4 (conflict-free)
    constexpr int BSTR = TRANSB ? 36 : 72;
    constexpr int BROW = TRANSB ? BN : BK;

    __shared__ __align__(16) float As[2][BM][ASTR];
    __shared__ __align__(16) float Bs[2][BROW][BSTR];

    const int z = blockIdx.z;
    const float* B = Bm0;
    const float* bias = bias0;
    float* C = C0;
    if (flags & 8) {
        if (z == 1) { B = Bm1; bias = bias1; C = C1; }
        else if (z == 2) { B = Bm2; bias = bias2; C = C2; }
    } else {
        A += boff(amode, sA, z);
        B += boff(bmode, sB, z);
        C += boff(cmode, sC, z);
        if (res) res += boff(cmode, sC, z);
    }

    const int rowBase = blockIdx.y * BM;
    const int colBase = blockIdx.x * BN;
    const int tid = threadIdx.x;
    const int lane = tid & 31;
    const int gid = lane >> 2, tid4 = lane & 3;
    const int w = tid >> 5;
    const int wm = (w >> 1) * 32;
    const int wn = (w & 1) * 32;

    float acc[2][4][4] = {};

    auto loadA = [&](int k0, int buf) {
        #pragma unroll
        for (int i = 0; i < 4; i++) {
            int c = tid + i * 128;
            int m = c >> 3, kc = c & 7;
            cp_async16(&As[buf][m][kc * 4],
                       &A[(long long)(rowBase + m) * lda + k0 + kc * 4]);
        }
    };
    auto loadB = [&](int k0, int buf) {
        if constexpr (TRANSB) {
            #pragma unroll
            for (int i = 0; i < 4; i++) {
                int c = tid + i * 128;
                int n = c >> 3, kc = c & 7;
                cp_async16(&Bs[buf][n][kc * 4],
                           &B[(long long)(colBase + n) * ldb + k0 + kc * 4]);
            }
        } else {
            #pragma unroll
            for (int i = 0; i < 4; i++) {
                int c = tid + i * 128;
                int k = c >> 4, nc = c & 15;
                cp_async16(&Bs[buf][k][nc * 4],
                           &B[(long long)(k0 + k) * ldb + colBase + nc * 4]);
            }
        }
    };

    const int NIT = K / BK;
    loadA(0, 0); loadB(0, 0);
    CP_COMMIT();

    for (int it = 0; it < NIT; it++) {
        const int cur = it & 1;
        if (it + 1 < NIT) { loadA((it + 1) * BK, cur ^ 1); loadB((it + 1) * BK, cur ^ 1); }
        CP_COMMIT();
        CP_WAIT1();
        __syncthreads();

        #pragma unroll
        for (int ks = 0; ks < 4; ks++) {
            const int kk = ks * 8;
            uint32_t ah[2][4], al[2][4], bh[4][2], bl[4][2];
            #pragma unroll
            for (int mt = 0; mt < 2; mt++) {
                int m = wm + mt * 16 + gid;
                split_tf32(As[cur][m][kk + tid4],          ah[mt][0], al[mt][0]);
                split_tf32(As[cur][m + 8][kk + tid4],      ah[mt][1], al[mt][1]);
                split_tf32(As[cur][m][kk + tid4 + 4],      ah[mt][2], al[mt][2]);
                split_tf32(As[cur][m + 8][kk + tid4 + 4],  ah[mt][3], al[mt][3]);
            }
            #pragma unroll
            for (int nt = 0; nt < 4; nt++) {
                int n = wn + nt * 8 + gid;
                float b0, b1;
                if constexpr (TRANSB) {
                    b0 = Bs[cur][n][kk + tid4];
                    b1 = Bs[cur][n][kk + tid4 + 4];
                } else {
                    b0 = Bs[cur][kk + tid4][n];
                    b1 = Bs[cur][kk + tid4 + 4][n];
                }
                split_tf32(b0, bh[nt][0], bl[nt][0]);
                split_tf32(b1, bh[nt][1], bl[nt][1]);
            }
            #pragma unroll
            for (int mt = 0; mt < 2; mt++)
                #pragma unroll
                for (int nt = 0; nt < 4; nt++) {
                    mma_tf32(acc[mt][nt], al[mt], bh[nt]);   // lo*hi
                    mma_tf32(acc[mt][nt], ah[mt], bl[nt]);   // hi*lo
                    mma_tf32(acc[mt][nt], ah[mt], bh[nt]);   // hi*hi
                }
        }
        __syncthreads();
    }

    // epilogue
    #pragma unroll
    for (int mt = 0; mt < 2; mt++) {
        #pragma unroll
        for (int nt = 0; nt < 4; nt++) {
            int r0 = rowBase + wm + mt * 16 + gid;
            int col = colBase + wn + nt * 8 + tid4 * 2;
            #pragma unroll
            for (int half = 0; half < 2; half++) {
                int r = r0 + half * 8;
                float v0 = acc[mt][nt][half * 2 + 0] * scale;
                float v1 = acc[mt][nt][half * 2 + 1] * scale;
                if (flags & 1) { v0 += bias[col]; v1 += bias[col + 1]; }
                if (flags & 4) {
                    v0 = 0.5f * v0 * (1.f + erff(v0 * 0.7071067811865475f));
                    v1 = 0.5f * v1 * (1.f + erff(v1 * 0.7071067811865475f));
                }
                if (flags & 2) {
                    float2 rv = *(const float2*)&res[(long long)r * ldr + col];
                    v0 += rv.x; v1 += rv.y;
                }
                float2 out; out.x = v0; out.y = v1;
                *(float2*)&C[(long long)r * ldc + col] = out;
            }
        }
    }
}

// ---------------- x = LN(src + pos) ----------------
__global__ void addposln_kernel(const float* __restrict__ q_emb,
                                const float* __restrict__ a_emb,
                                const float* __restrict__ pos,
                                const float* __restrict__ w,
                                const float* __restrict__ b)
{
    int row = blockIdx.x;
    int t = row & (Tt - 1);
    const float* src = (row < 512) ? (q_emb + (long long)row * Dm)
                                   : (a_emb + (long long)(row - 512) * Dm);
    int d0 = threadIdx.x, d1 = d0 + 256;
    float x0 = src[d0] + pos[t * Dm + d0];
    float x1 = src[d1] + pos[t * Dm + d1];
    float mean = blockReduceSum(x0 + x1) * (1.f / Dm);
    float e0 = x0 - mean, e1 = x1 - mean;
    float var = blockReduceSum(e0 * e0 + e1 * e1) * (1.f / Dm);
    float inv = 1.f / sqrtf(var + 1e-12f);
    g_x[(long long)row * Dm + d0] = w[d0] * e0 * inv + b[d0];
    g_x[(long long)row * Dm + d1] = w[d1] * e1 * inv + b[d1];
}

// ---------------- Y = LN(X) ----------------
__global__ void ln_kernel(const float* __restrict__ X,
                          const float* __restrict__ w,
                          const float* __restrict__ b,
                          float* __restrict__ Y)
{
    int row = blockIdx.x;
    int d0 = threadIdx.x, d1 = d0 + 256;
    float x0 = X[(long long)row * Dm + d0];
    float x1 = X[(long long)row * Dm + d1];
    float mean = blockReduceSum(x0 + x1) * (1.f / Dm);
    float e0 = x0 - mean, e1 = x1 - mean;
    float var = blockReduceSum(e0 * e0 + e1 * e1) * (1.f / Dm);
    float inv = 1.f / sqrtf(var + 1e-12f);
    Y[(long long)row * Dm + d0] = w[d0] * e0 * inv + b[d0];
    Y[(long long)row * Dm + d1] = w[d1] * e1 * inv + b[d1];
}

// ---------------- softmax over rows of 128 (optional x1000 sharpening) ----------------
__global__ void softmax_kernel(float* __restrict__ S, int sharpen)
{
    float* p = S + (long long)blockIdx.x * 128;
    int t = threadIdx.x, lane = t & 31, w = t >> 5;
    __shared__ float sm[4], ss[4], sm2[4], ss2[4];
    float v = p[t];
    float m = v;
    #pragma unroll
    for (int o = 16; o; o >>= 1) m = fmaxf(m, __shfl_xor_sync(0xffffffffu, m, o));
    if (lane == 0) sm[w] = m;
    __syncthreads();
    m = fmaxf(fmaxf(sm[0], sm[1]), fmaxf(sm[2], sm[3]));
    float e = expf(v - m);
    float s = e;
    #pragma unroll
    for (int o = 16; o; o >>= 1) s += __shfl_xor_sync(0xffffffffu, s, o);
    if (lane == 0) ss[w] = s;
    __syncthreads();
    s = ss[0] + ss[1] + ss[2] + ss[3];
    float prob = e / s;
    if (sharpen) {
        float zz = 1000.f * prob;
        float m2 = zz;
        #pragma unroll
        for (int o = 16; o; o >>= 1) m2 = fmaxf(m2, __shfl_xor_sync(0xffffffffu, m2, o));
        if (lane == 0) sm2[w] = m2;
        __syncthreads();
        m2 = fmaxf(fmaxf(sm2[0], sm2[1]), fmaxf(sm2[2], sm2[3]));
        float e2 = expf(zz - m2);
        float s2 = e2;
        #pragma unroll
        for (int o = 16; o; o >>= 1) s2 += __shfl_xor_sync(0xffffffffu, s2, o);
        if (lane == 0) ss2[w] = s2;
        __syncthreads();
        s2 = ss2[0] + ss2[1] + ss2[2] + ss2[3];
        prob = e2 / s2;
    }
    p[t] = prob;
}

// ---------------- Qc/Kc: out[row,c] = dot(X[row,:], ce[c,:]) ----------------
__global__ void proj_concept(const float* __restrict__ X,
                             const float* __restrict__ ce,
                             float* __restrict__ out)
{
    int row = blockIdx.x;
    const float* xr = X + (long long)row * Dm;
    for (int c = 0; c < 5; c++) {
        float partial = 0.f;
        for (int d = threadIdx.x; d < Dm; d += blockDim.x)
            partial += xr[d] * ce[c * Dm + d];
        float tot = blockReduceSum(partial);
        if (threadIdx.x == 0) out[row * 5 + c] = tot;
    }
}

// ---------------- G = ce @ ce^T (5x5) ----------------
__global__ void gram_kernel(const float* __restrict__ ce)
{
    int i = threadIdx.x;
    if (i < 25) {
        int a = i / 5, b2 = i % 5;
        float s = 0.f;
        for (int d = 0; d < Dm; d++) s += ce[a * Dm + d] * ce[b2 * Dm + d];
        g_G[i] = s;
    }
}

// ---------------- add concept correction terms to sim scores ----------------
__global__ void simcorr_kernel(const float* __restrict__ qa,
                               const float* __restrict__ aq)
{
    int b = blockIdx.x >> 7;
    int t = blockIdx.x & 127;
    int s = threadIdx.x;
    __shared__ float sQc[5], sG[25];
    if (s < 5)  sQc[s] = g_Qc[(b * Tt + t) * 5 + s];
    if (s < 25) sG[s] = g_G[s];
    __syncthreads();
    long long base_qa = ((long long)(b * Tt + t) * Tt + s) * 5;
    long long base_aq = ((long long)(b * Tt + s) * Tt + t) * 5;
    float qa5[5], aq5[5], kc[5];
    #pragma unroll
    for (int c = 0; c < 5; c++) {
        qa5[c] = qa[base_qa + c];
        aq5[c] = aq[base_aq + c];
        kc[c]  = g_Kc[(b * Tt + s) * 5 + c];
    }
    float acc = g_sc[b * Tt * Tt + t * Tt + s];
    #pragma unroll
    for (int c = 0; c < 5; c++) acc += aq5[c] * sQc[c] + qa5[c] * kc[c];
    #pragma unroll
    for (int c = 0; c < 5; c++)
        #pragma unroll
        for (int c2 = 0; c2 < 5; c2++) acc += qa5[c] * aq5[c2] * sG[c * 5 + c2];
    g_sc[b * Tt * Tt + t * Tt + s] = acc;
}

// ---------------- pbar[b,s] = mean_t p[b,t,s] ----------------
__global__ void pbar_kernel()
{
    int b = blockIdx.x, s = threadIdx.x;
    float a = 0.f;
    for (int t = 0; t < Tt; t++) a += g_sc[b * Tt * Tt + t * Tt + s];
    g_pbar[b * Tt + s] = a * (1.f / Tt);
}

// ---------------- Rbar[b,c] = mean_t sum_s p[b,t,s]*aq[b,s,t,c] ----------------
__global__ void rbar_kernel(const float* __restrict__ aq)
{
    int b = blockIdx.x, t = threadIdx.x;
    float r[5] = {0.f, 0.f, 0.f, 0.f, 0.f};
    for (int s = 0; s < Tt; s++) {
        float pv = g_sc[b * Tt * Tt + t * Tt + s];
        long long base = ((long long)(b * Tt + s) * Tt + t) * 5;
        #pragma unroll
        for (int c = 0; c < 5; c++) r[c] += pv * aq[base + c];
    }
    for (int c = 0; c < 5; c++) {
        float tot = blockReduceSum(r[c]);
        if (t == 0) g_Rbar[b * 5 + c] = tot * (1.f / Tt);
    }
}

// ---------------- final ----------------
__global__ void final_kernel(const float* __restrict__ ce,
                             const float* __restrict__ cls_w,
                             const float* __restrict__ cls_b,
                             float* __restrict__ out)
{
    __shared__ float m[Dm];
    int b = blockIdx.x, d = threadIdx.x;
    float acc = 0.f;
    for (int s = 0; s < Tt; s++)
        acc += g_pbar[b * Tt + s] * g_ks[(long long)(b * Tt + s) * Dm + d];
    #pragma unroll
    for (int c = 0; c < 5; c++) acc += g_Rbar[b * 5 + c] * ce[c * Dm + d];
    m[d] = acc;
    __syncthreads();
    if (d < 3) {
        float o = cls_b[d];
        for (int k2 = 0; k2 < Dm; k2++) o += m[k2] * cls_w[k2 * 3 + d];
        out[b * 3 + d] = o;
    }
}

// ---------------- host ----------------
extern "C" void kernel_launch(void* const* d_in, const int* in_sizes, int n_in,
                              void* d_out, int out_size)
{
    const float* q_emb    = (const float*)d_in[0];
    const float* a_emb    = (const float*)d_in[1];
    const float* qa_rel   = (const float*)d_in[2];
    const float* aq_rel   = (const float*)d_in[3];
    const float* ce       = (const float*)d_in[4];
    const float* pos_emb  = (const float*)d_in[5];
    const float* pe_w     = (const float*)d_in[6];
    const float* pe_b     = (const float*)d_in[7];
    const float* Wq       = (const float*)d_in[8];
    const float* bq       = (const float*)d_in[9];
    const float* Wk       = (const float*)d_in[10];
    const float* bk       = (const float*)d_in[11];
    const float* Wv       = (const float*)d_in[12];
    const float* bv       = (const float*)d_in[13];
    const float* Wo       = (const float*)d_in[14];
    const float* bo       = (const float*)d_in[15];
    const float* ff1w     = (const float*)d_in[16];
    const float* ff1b     = (const float*)d_in[17];
    const float* ff2w     = (const float*)d_in[18];
    const float* ff2b     = (const float*)d_in[19];
    const float* lnin_w   = (const float*)d_in[20];
    const float* lnin_b   = (const float*)d_in[21];
    const float* lnout_w  = (const float*)d_in[22];
    const float* lnout_b  = (const float*)d_in[23];
    const float* sim_Wq   = (const float*)d_in[24];
    const float* sim_bq   = (const float*)d_in[25];
    const float* sim_Wk   = (const float*)d_in[26];
    const float* sim_bk   = (const float*)d_in[27];
    const float* cls_w    = (const float*)d_in[28];
    const float* cls_b    = (const float*)d_in[29];

    float *x, *q, *k, *v, *h, *ff, *s, *qs, *ks, *sc, *Qc, *Kc;
    cudaGetSymbolAddress((void**)&x,  g_x);
    cudaGetSymbolAddress((void**)&q,  g_q);
    cudaGetSymbolAddress((void**)&k,  g_k);
    cudaGetSymbolAddress((void**)&v,  g_v);
    cudaGetSymbolAddress((void**)&h,  g_h);
    cudaGetSymbolAddress((void**)&ff, g_ff);
    cudaGetSymbolAddress((void**)&s,  g_s);
    cudaGetSymbolAddress((void**)&qs, g_qs);
    cudaGetSymbolAddress((void**)&ks, g_ks);
    cudaGetSymbolAddress((void**)&sc, g_sc);
    cudaGetSymbolAddress((void**)&Qc, g_Qc);
    cudaGetSymbolAddress((void**)&Kc, g_Kc);

    const float attn_scale = 0.08838834764831845f;  // 1/sqrt(128)
    dim3 blk(128);

    addposln_kernel<<<ROWS, 256>>>(q_emb, a_emb, pos_emb, pe_w, pe_b);

    for (int i = 0; i < NLAYER; i++) {
        const float* wq = Wq + (long long)i * Dm * Dm;
        const float* wk = Wk + (long long)i * Dm * Dm;
        const float* wv = Wv + (long long)i * Dm * Dm;
        const float* wo = Wo + (long long)i * Dm * Dm;
        const float* f1w = ff1w + (long long)i * Dm * DFFm;
        const float* f2w = ff2w + (long long)i * DFFm * Dm;

        // fused QKV: z selects (W, bias, out). 384 CTAs
        gemm_tc<0><<<dim3(8, 16, 3), blk>>>(
            x, Dm, wq, wk, wv, Dm, bq + i * Dm, bk + i * Dm, bv + i * Dm,
            nullptr, 0, q, k, v, Dm, Dm, 1 | 8, 1.f, 0, 0, 0, 0, 0, 0);

        // S = scale * Q K^T per (seq,head). 128 CTAs
        gemm_tc<1><<<dim3(2, 2, 32), blk>>>(
            q, Dm, k, nullptr, nullptr, Dm, nullptr, nullptr, nullptr,
            nullptr, 0, s, nullptr, nullptr, Tt, DK, 0, attn_scale,
            1, 0, 1, 0, 0, (long long)Tt * Tt);
        softmax_kernel<<<32 * Tt, 128>>>(s, 0);
        // O = P V (head-interleaved into g_h). 128 CTAs
        gemm_tc<0><<<dim3(2, 2, 32), blk>>>(
            s, Tt, v, nullptr, nullptr, Dm, nullptr, nullptr, nullptr,
            nullptr, 0, h, nullptr, nullptr, Dm, Tt, 0, 1.f,
            0, (long long)Tt * Tt, 1, 0, 1, 0);
        // x = x + O @ Wo + bo. 128 CTAs
        gemm_tc<0><<<dim3(8, 16, 1), blk>>>(
            h, Dm, wo, nullptr, nullptr, Dm, bo + i * Dm, nullptr, nullptr,
            x, Dm, x, nullptr, nullptr, Dm, Dm, 1 | 2, 1.f, 0, 0, 0, 0, 0, 0);
        // h = LN_in(x)
        ln_kernel<<<ROWS, 256>>>(x, lnin_w + i * Dm, lnin_b + i * Dm, h);
        // ff = gelu(h @ ff1 + b1). 512 CTAs
        gemm_tc<0><<<dim3(32, 16, 1), blk>>>(
            h, Dm, f1w, nullptr, nullptr, DFFm, ff1b + i * DFFm, nullptr, nullptr,
            nullptr, 0, ff, nullptr, nullptr, DFFm, Dm, 1 | 4, 1.f, 0, 0, 0, 0, 0, 0);
        // q(tmp) = x + ff @ ff2 + b2. 128 CTAs
        gemm_tc<0><<<dim3(8, 16, 1), blk>>>(
            ff, DFFm, f2w, nullptr, nullptr, Dm, ff2b + i * Dm, nullptr, nullptr,
            x, Dm, q, nullptr, nullptr, Dm, DFFm, 1 | 2, 1.f, 0, 0, 0, 0, 0, 0);
        // x = LN_out(q)
        ln_kernel<<<ROWS, 256>>>(q, lnout_w + i * Dm, lnout_b + i * Dm, x);
    }

    // ---- SimAttn tail (3xTF32 as well) ----
    gemm_tc<0><<<dim3(8, 8, 1), blk>>>(
        x, Dm, sim_Wq, nullptr, nullptr, Dm, sim_bq, nullptr, nullptr,
        nullptr, 0, qs, nullptr, nullptr, Dm, Dm, 1, 1.f, 0, 0, 0, 0, 0, 0);
    gemm_tc<0><<<dim3(8, 8, 1), blk>>>(
        x + 512 * Dm, Dm, sim_Wk, nullptr, nullptr, Dm, sim_bk, nullptr, nullptr,
        nullptr, 0, ks, nullptr, nullptr, Dm, Dm, 1, 1.f, 0, 0, 0, 0, 0, 0);

    proj_concept<<<512, 256>>>(qs, ce, Qc);
    proj_concept<<<512, 256>>>(ks, ce, Kc);
    gram_kernel<<<1, 32>>>(ce);

    // base scores = q_sim @ k_sim^T per batch. 16 CTAs
    gemm_tc<1><<<dim3(2, 2, 4), blk>>>(
        qs, Dm, ks, nullptr, nullptr, Dm, nullptr, nullptr, nullptr,
        nullptr, 0, sc, nullptr, nullptr, Tt, Dm, 0, 1.f,
        0, (long long)Tt * Dm, 0, (long long)Tt * Dm, 0, (long long)Tt * Tt);
    simcorr_kernel<<<512, 128>>>(qa_rel, aq_rel);
    softmax_kernel<<<512, 128>>>(sc, 1);

    pbar_kernel<<<4, 128>>>();
    rbar_kernel<<<4, 128>>>(aq_rel);
    final_kernel<<<4, 512>>>(ce, cls_w, cls_b, (float*)d_out);
}